// round 12
// baseline (speedup 1.0000x reference)
#include <cuda_runtime.h>
#include <cuda_fp16.h>

#define N_NODES 50000
#define F 64
#define HDIM 128          // output cols of the dual GEMM (64 + 64)
#define BSTRIDE 128       // bucket region per node (4 reps x 32 cap)
#define BCAP 32
#define NREP 4

// Scratch: __device__ globals (allocation-free, graph-capturable).
// Invariant: g_cursor all-zero at kernel_launch entry (zero at module load;
// aggx_kernel re-zeroes after reading, every run).
__device__ __align__(16) __half g_xh[(size_t)N_NODES * F];   // x in fp16
__device__ __align__(16) __half g_a[(size_t)N_NODES * F];    // aggregated features fp16
__device__ __align__(16) __half g_wt[HDIM * F];              // Wt[c][k] fp16 (n-major)
__device__ float g_dinv[N_NODES];
__device__ float g_invdeg[N_NODES];
__device__ __align__(16) int g_cursor[NREP * N_NODES];       // per (node, rep)
__device__ int g_srcsorted[(size_t)N_NODES * BSTRIDE];       // bucketed src ids

// ---------------------------------------------------------------------------
// Fused: blocks [0, nScatter) bucket-scatter edges; blocks [nScatter, ...)
// convert x -> fp16 and W -> fp16 n-major.
// ---------------------------------------------------------------------------
__global__ void __launch_bounds__(256) scatter_prep_kernel(
    const int* __restrict__ ei, int E, int nScatter,
    const float* __restrict__ x,
    const float* __restrict__ W1,
    const float* __restrict__ W2) {

    if ((int)blockIdx.x < nScatter) {
        int t = blockIdx.x * 256 + threadIdx.x;
        int rep = t & (NREP - 1);
        int base = t * 4;
        if (base + 4 <= E) {
            int4 s = *(const int4*)(ei + base);
            int4 d = *(const int4*)(ei + E + base);
            int p0 = atomicAdd(&g_cursor[d.x * NREP + rep], 1);
            int p1 = atomicAdd(&g_cursor[d.y * NREP + rep], 1);
            int p2 = atomicAdd(&g_cursor[d.z * NREP + rep], 1);
            int p3 = atomicAdd(&g_cursor[d.w * NREP + rep], 1);
            g_srcsorted[(size_t)d.x * BSTRIDE + rep * BCAP + p0] = s.x;
            g_srcsorted[(size_t)d.y * BSTRIDE + rep * BCAP + p1] = s.y;
            g_srcsorted[(size_t)d.z * BSTRIDE + rep * BCAP + p2] = s.z;
            g_srcsorted[(size_t)d.w * BSTRIDE + rep * BCAP + p3] = s.w;
        } else {
            for (int e = base; e < E; e++) {
                int d = ei[E + e];
                int pos = atomicAdd(&g_cursor[d * NREP + rep], 1);
                g_srcsorted[(size_t)d * BSTRIDE + rep * BCAP + pos] = ei[e];
            }
        }
        return;
    }

    int p = (blockIdx.x - nScatter) * 256 + threadIdx.x;
    if (p < N_NODES * F / 4) {
        float4 v = *(const float4*)(x + (size_t)p * 4);
        __half2 h0 = __floats2half2_rn(v.x, v.y);
        __half2 h1 = __floats2half2_rn(v.z, v.w);
        uint2 o = make_uint2(*reinterpret_cast<unsigned*>(&h0),
                             *reinterpret_cast<unsigned*>(&h1));
        *(uint2*)(g_xh + (size_t)p * 4) = o;
    }
    if (p < HDIM * F) {
        int c = p >> 6, k = p & 63;
        float v = (c < 64) ? W1[k * 64 + c] : W2[k * 64 + (c - 64)];
        g_wt[c * F + k] = __float2half_rn(v);
    }
}

// ---------------------------------------------------------------------------
// deg = sum of 4 cursors + 1 (self loop) -> dinv, invdeg.
// ---------------------------------------------------------------------------
__global__ void __launch_bounds__(256) dinv_kernel() {
    int i = blockIdx.x * blockDim.x + threadIdx.x;
    if (i < N_NODES) {
        int4 c = *(const int4*)(g_cursor + i * NREP);
        float dg = (float)(c.x + c.y + c.z + c.w + 1);
        g_invdeg[i] = 1.0f / dg;
        g_dinv[i]   = rsqrtf(dg);
    }
}

// ---------------------------------------------------------------------------
// Aggregate x: a[dst] = (sum norm*xh[src] + dinv^2*xh[dst]) / deg.
// FOUR nodes per warp: quarter q = lane>>3 -> node 4w+q; lane owns 8 cols
// via uint4 (16B; 8 lanes x 16B = one 128B row). Each warp-instruction
// advances 4 edges. Subchunk trip count is warp-maxed across quarters;
// padded entries have nrm=0 (harmless). Re-zeroes cursors at the end.
// ---------------------------------------------------------------------------
__device__ __forceinline__ void agg_step8(
    int sv, float nv, int qb, int hl,
    float* acc) {
    #pragma unroll
    for (int u = 0; u < 8; u++) {
        int   ss = __shfl_sync(0xffffffffu, sv, qb + u);
        float nn = __shfl_sync(0xffffffffu, nv, qb + u);
        uint4 v = *((const uint4*)(g_xh + (size_t)ss * F) + hl);
        float2 f0 = __half22float2(*reinterpret_cast<__half2*>(&v.x));
        float2 f1 = __half22float2(*reinterpret_cast<__half2*>(&v.y));
        float2 f2 = __half22float2(*reinterpret_cast<__half2*>(&v.z));
        float2 f3 = __half22float2(*reinterpret_cast<__half2*>(&v.w));
        acc[0] = fmaf(nn, f0.x, acc[0]);
        acc[1] = fmaf(nn, f0.y, acc[1]);
        acc[2] = fmaf(nn, f1.x, acc[2]);
        acc[3] = fmaf(nn, f1.y, acc[3]);
        acc[4] = fmaf(nn, f2.x, acc[4]);
        acc[5] = fmaf(nn, f2.y, acc[5]);
        acc[6] = fmaf(nn, f3.x, acc[6]);
        acc[7] = fmaf(nn, f3.y, acc[7]);
    }
}

__global__ void __launch_bounds__(256) aggx_kernel() {
    int w    = (blockIdx.x * blockDim.x + threadIdx.x) >> 5;
    int lane = threadIdx.x & 31;
    int q    = lane >> 3;          // quarter 0..3
    int hl   = lane & 7;           // lane within quarter
    int node = w * 4 + q;
    if (node >= N_NODES) return;   // N_NODES % 4 == 0: whole warp exits together

    float di = g_dinv[node];
    int4 cc = *(const int4*)(g_cursor + node * NREP);
    if (hl == 0)
        *(int4*)(g_cursor + node * NREP) = make_int4(0, 0, 0, 0);
    int cnt_arr[4] = {cc.x, cc.y, cc.z, cc.w};

    // self-loop term: di*di * xh[node], lane's 8 cols
    float acc[8];
    {
        uint4 u = *((const uint4*)(g_xh + (size_t)node * F) + hl);
        float2 f0 = __half22float2(*reinterpret_cast<__half2*>(&u.x));
        float2 f1 = __half22float2(*reinterpret_cast<__half2*>(&u.y));
        float2 f2 = __half22float2(*reinterpret_cast<__half2*>(&u.z));
        float2 f3 = __half22float2(*reinterpret_cast<__half2*>(&u.w));
        float self = di * di;
        acc[0] = self * f0.x; acc[1] = self * f0.y;
        acc[2] = self * f1.x; acc[3] = self * f1.y;
        acc[4] = self * f2.x; acc[5] = self * f2.y;
        acc[6] = self * f3.x; acc[7] = self * f3.y;
    }

    int qb = q << 3;               // shfl source base for my quarter

    #pragma unroll 1
    for (int rep = 0; rep < NREP; rep++) {
        int cnt = cnt_arr[rep];
        const int* src = g_srcsorted + (size_t)node * BSTRIDE + rep * BCAP;

        // preload up to 32 entries: register j holds entries 8j + hl
        int   s0 = node, s1 = node, s2 = node, s3 = node;
        float n0 = 0.f, n1 = 0.f, n2 = 0.f, n3 = 0.f;
        if (hl < cnt)      { s0 = src[hl];      n0 = di * g_dinv[s0]; }
        if (hl +  8 < cnt) { s1 = src[hl +  8]; n1 = di * g_dinv[s1]; }
        if (hl + 16 < cnt) { s2 = src[hl + 16]; n2 = di * g_dinv[s2]; }
        if (hl + 24 < cnt) { s3 = src[hl + 24]; n3 = di * g_dinv[s3]; }

        int nsub = (cnt + 7) >> 3;                       // 0..4
        int m = max(nsub, __shfl_xor_sync(0xffffffffu, nsub, 8));
        m = max(m, __shfl_xor_sync(0xffffffffu, m, 16)); // warp max

        if (m > 0) agg_step8(s0, n0, qb, hl, acc);
        if (m > 1) agg_step8(s1, n1, qb, hl, acc);
        if (m > 2) agg_step8(s2, n2, qb, hl, acc);
        if (m > 3) agg_step8(s3, n3, qb, hl, acc);
    }

    float inv = g_invdeg[node];
    __half2 h0 = __floats2half2_rn(acc[0] * inv, acc[1] * inv);
    __half2 h1 = __floats2half2_rn(acc[2] * inv, acc[3] * inv);
    __half2 h2 = __floats2half2_rn(acc[4] * inv, acc[5] * inv);
    __half2 h3 = __floats2half2_rn(acc[6] * inv, acc[7] * inv);
    uint4 o = make_uint4(*reinterpret_cast<unsigned*>(&h0),
                         *reinterpret_cast<unsigned*>(&h1),
                         *reinterpret_cast<unsigned*>(&h2),
                         *reinterpret_cast<unsigned*>(&h3));
    *((uint4*)(g_a + (size_t)node * F) + hl) = o;
}

// ---------------------------------------------------------------------------
// Fused dual-GEMM + epilogue: out = relu(a@W1) * sigmoid(a@W2).
// A-fragments hoisted (nt-invariant); nt loop keeps only 8 live accumulators
// -> low register pressure, high occupancy. Register-local relu*sigmoid.
// ---------------------------------------------------------------------------
__global__ void __launch_bounds__(256) gemm_epi_kernel(float* __restrict__ out) {
    __shared__ __half xs[128][72];
    __shared__ __half ws[128][72];

    int tid = threadIdx.x;
    int row0 = blockIdx.x * 128;

    for (int i = tid; i < 128 * 8; i += 256) {
        int r = i >> 3, ch = i & 7;
        int row = row0 + r;
        uint4 v = make_uint4(0u, 0u, 0u, 0u);
        if (row < N_NODES) v = *(const uint4*)(g_a + (size_t)row * F + ch * 8);
        *(uint4*)&xs[r][ch * 8] = v;
    }
    for (int i = tid; i < 128 * 8; i += 256) {
        int r = i >> 3, ch = i & 7;
        *(uint4*)&ws[r][ch * 8] = *(const uint4*)(g_wt + r * F + ch * 8);
    }
    __syncthreads();

    int warp = tid >> 5, lane = tid & 31;
    int g = lane >> 2, t = lane & 3;
    int wrow = warp * 16;

    // Hoist nt-invariant A fragments: a[ks][0..3]
    unsigned afr[4][4];
    #pragma unroll
    for (int ks = 0; ks < 4; ks++) {
        int kb = ks * 16;
        afr[ks][0] = *(const unsigned*)&xs[wrow + g][kb + 2 * t];
        afr[ks][1] = *(const unsigned*)&xs[wrow + g + 8][kb + 2 * t];
        afr[ks][2] = *(const unsigned*)&xs[wrow + g][kb + 2 * t + 8];
        afr[ks][3] = *(const unsigned*)&xs[wrow + g + 8][kb + 2 * t + 8];
    }

    int r1 = row0 + wrow + g;
    int r2 = r1 + 8;

    #pragma unroll
    for (int nt = 0; nt < 8; nt++) {
        float c1[4] = {0.f, 0.f, 0.f, 0.f};   // layer1 (cols nt*8..)
        float c2[4] = {0.f, 0.f, 0.f, 0.f};   // layer2 (cols 64+nt*8..)
        #pragma unroll
        for (int ks = 0; ks < 4; ks++) {
            int kb = ks * 16;
            unsigned b0 = *(const unsigned*)&ws[nt * 8 + g][kb + 2 * t];
            unsigned b1 = *(const unsigned*)&ws[nt * 8 + g][kb + 2 * t + 8];
            asm volatile(
                "mma.sync.aligned.m16n8k16.row.col.f32.f16.f16.f32 "
                "{%0,%1,%2,%3}, {%4,%5,%6,%7}, {%8,%9}, {%0,%1,%2,%3};"
                : "+f"(c1[0]), "+f"(c1[1]), "+f"(c1[2]), "+f"(c1[3])
                : "r"(afr[ks][0]), "r"(afr[ks][1]), "r"(afr[ks][2]), "r"(afr[ks][3]),
                  "r"(b0), "r"(b1));
            unsigned d0 = *(const unsigned*)&ws[(nt + 8) * 8 + g][kb + 2 * t];
            unsigned d1 = *(const unsigned*)&ws[(nt + 8) * 8 + g][kb + 2 * t + 8];
            asm volatile(
                "mma.sync.aligned.m16n8k16.row.col.f32.f16.f16.f32 "
                "{%0,%1,%2,%3}, {%4,%5,%6,%7}, {%8,%9}, {%0,%1,%2,%3};"
                : "+f"(c2[0]), "+f"(c2[1]), "+f"(c2[2]), "+f"(c2[3])
                : "r"(afr[ks][0]), "r"(afr[ks][1]), "r"(afr[ks][2]), "r"(afr[ks][3]),
                  "r"(d0), "r"(d1));
        }

        int col = nt * 8 + 2 * t;
        if (r1 < N_NODES) {
            float2 o;
            o.x = fmaxf(c1[0], 0.0f) * (1.0f / (1.0f + expf(-c2[0])));
            o.y = fmaxf(c1[1], 0.0f) * (1.0f / (1.0f + expf(-c2[1])));
            *(float2*)(out + (size_t)r1 * F + col) = o;
        }
        if (r2 < N_NODES) {
            float2 o;
            o.x = fmaxf(c1[2], 0.0f) * (1.0f / (1.0f + expf(-c2[2])));
            o.y = fmaxf(c1[3], 0.0f) * (1.0f / (1.0f + expf(-c2[3])));
            *(float2*)(out + (size_t)r2 * F + col) = o;
        }
    }
}

// ---------------------------------------------------------------------------
extern "C" void kernel_launch(void* const* d_in, const int* in_sizes, int n_in,
                              void* d_out, int out_size) {
    const float* x  = (const float*)d_in[0];
    const int*   ei = (const int*)d_in[1];   // int32 (JAX x64 disabled)
    const float* W1 = (const float*)d_in[2];
    const float* W2 = (const float*)d_in[3];
    float* out = (float*)d_out;

    int E  = in_sizes[1] / 2;
    int T4 = (E + 3) / 4;
    int S  = (T4 + 255) / 256;                       // scatter blocks (first)
    int P  = (N_NODES * F / 4 + 255) / 256;          // prep blocks

    scatter_prep_kernel<<<S + P, 256>>>(ei, E, S, x, W1, W2);
    dinv_kernel<<<(N_NODES + 255) / 256, 256>>>();
    aggx_kernel<<<(N_NODES / 4 * 32 + 255) / 256, 256>>>();  // 4 nodes per warp
    gemm_epi_kernel<<<(N_NODES + 127) / 128, 256>>>(out);
}